// round 8
// baseline (speedup 1.0000x reference)
#include <cuda_runtime.h>
#include <math.h>
#include <stdint.h>

static constexpr int B_ = 8;
static constexpr int C_ = 256;
static constexpr int N_ = 2048;
static constexpr int M_ = 2048;

// Scratch (no cudaMalloc allowed)
__device__ float g_q[B_*C_*N_];
__device__ float g_k[B_*C_*M_];
__device__ float g_v[B_*C_*M_];
__device__ float g_attn[B_*C_*N_];
__device__ float g_mo[B_*C_*N_];
__device__ float g_h[B_*2*C_*N_];

// ---------------------------------------------------------------------------
// GEMM: Y[b][o][n] = epi( sum_i W[o][i] * X[b][i][n] + bias[o] )   (unchanged)
// ---------------------------------------------------------------------------
template<int MODE>
__global__ void __launch_bounds__(256) gemm_epi(
    const float* __restrict__ W, const float* __restrict__ bias,
    const float* __restrict__ Xa, const float* __restrict__ Xb,
    float* __restrict__ Y, int Cout, int Cin, int Ca,
    const float* __restrict__ e0, const float* __restrict__ e1,
    const float* __restrict__ e2, const float* __restrict__ e3)
{
    __shared__ float Wt[16*68];
    __shared__ float Xs[16*64];

    const int b  = blockIdx.z;
    const int o0 = blockIdx.y * 64;
    const int n0 = blockIdx.x * 64;
    const int t  = threadIdx.x;
    const int tx = t & 15, ty = t >> 4;
    const int Cb = Cin - Ca;

    float acc[4][4] = {};

    for (int i0 = 0; i0 < Cin; i0 += 16) {
        {
            const int o  = t >> 2;
            const int iq = (t & 3) << 2;
            float4 w4 = *(const float4*)&W[(size_t)(o0 + o) * Cin + i0 + iq];
            Wt[(iq+0)*68 + o] = w4.x;
            Wt[(iq+1)*68 + o] = w4.y;
            Wt[(iq+2)*68 + o] = w4.z;
            Wt[(iq+3)*68 + o] = w4.w;
        }
        #pragma unroll
        for (int r = 0; r < 4; r++) {
            int idx = r*256 + t;
            int ii = idx >> 6, nn = idx & 63;
            int ig = i0 + ii;
            float val;
            if (ig < Ca) val = Xa[((size_t)b*Ca + ig) * N_ + n0 + nn];
            else         val = Xb[((size_t)b*Cb + (ig - Ca)) * N_ + n0 + nn];
            Xs[ii*64 + nn] = val;
        }
        __syncthreads();
        #pragma unroll
        for (int kk = 0; kk < 16; kk++) {
            float4 a = *(const float4*)&Wt[kk*68 + 4*ty];
            float4 x = *(const float4*)&Xs[kk*64 + 4*tx];
            float av[4] = {a.x, a.y, a.z, a.w};
            float xv[4] = {x.x, x.y, x.z, x.w};
            #pragma unroll
            for (int i = 0; i < 4; i++)
                #pragma unroll
                for (int j = 0; j < 4; j++)
                    acc[i][j] = fmaf(av[i], xv[j], acc[i][j]);
        }
        __syncthreads();
    }

    float4 wvv;
    if constexpr (MODE == 1) {
        wvv = *(const float4*)&e0[(size_t)b * N_ + n0 + 4*tx];
    }
    #pragma unroll
    for (int i = 0; i < 4; i++) {
        const int o = o0 + 4*ty + i;
        const float bi = bias[o];
        float4 r;
        r.x = acc[i][0] + bi; r.y = acc[i][1] + bi;
        r.z = acc[i][2] + bi; r.w = acc[i][3] + bi;
        if constexpr (MODE == 1) {
            r.x *= wvv.x; r.y *= wvv.y; r.z *= wvv.z; r.w *= wvv.w;
        }
        if constexpr (MODE == 2) {
            float inv = e0[o] * rsqrtf(e3[o] + 1e-5f);
            float add = e1[o] - e2[o] * inv;
            r.x = fmaxf(fmaf(r.x, inv, add), 0.f);
            r.y = fmaxf(fmaf(r.y, inv, add), 0.f);
            r.z = fmaxf(fmaf(r.z, inv, add), 0.f);
            r.w = fmaxf(fmaf(r.w, inv, add), 0.f);
        }
        if constexpr (MODE == 3) {
            float4 res = *(const float4*)&e0[((size_t)b*Cout + o) * N_ + n0 + 4*tx];
            r.x += res.x; r.y += res.y; r.z += res.z; r.w += res.w;
        }
        *(float4*)&Y[((size_t)b*Cout + o) * N_ + n0 + 4*tx] = r;
    }
}

// ---------------------------------------------------------------------------
// Attention via mma.sync tf32 (FA2 style).
// CTA = 128 threads (4 warps), 64 n-rows per CTA (16 per warp), m-tiles of 64.
// Q fragments register-resident; K/V in smem [d][m] stride 72 (conflict-free
// fragment reads); P goes through a warp-private smem strip.
// ---------------------------------------------------------------------------
__device__ __forceinline__ uint32_t f2tf32(float f) {
    uint32_t r;
    asm("cvt.rna.tf32.f32 %0, %1;" : "=r"(r) : "f"(f));
    return r;
}

__device__ __forceinline__ void mma_tf32(
    float d[4], const uint32_t a[4], uint32_t b0, uint32_t b1, const float c[4])
{
    asm volatile(
        "mma.sync.aligned.m16n8k8.row.col.f32.tf32.tf32.f32 "
        "{%0,%1,%2,%3}, {%4,%5,%6,%7}, {%8,%9}, {%10,%11,%12,%13};"
        : "=f"(d[0]), "=f"(d[1]), "=f"(d[2]), "=f"(d[3])
        : "r"(a[0]), "r"(a[1]), "r"(a[2]), "r"(a[3]),
          "r"(b0), "r"(b1),
          "f"(c[0]), "f"(c[1]), "f"(c[2]), "f"(c[3]));
}

static constexpr int ST = 72;          // smem row stride (floats)
static constexpr int TILE_F = 64 * ST; // 4608 floats per buffer

__global__ void __launch_bounds__(128) attn_mma(
    const float* __restrict__ Q, const float* __restrict__ K,
    const float* __restrict__ V, float* __restrict__ O)
{
    extern __shared__ float sm[];
    float* Ks = sm;              // [64 d][ST]
    float* Vs = sm + TILE_F;     // [64 d][ST]
    float* Ps = sm + 2*TILE_F;   // Q stage / per-warp P strips / scratch

    const int bh = blockIdx.y;
    const int n0 = blockIdx.x * 64;
    const size_t base = (size_t)bh * 64 * 2048;
    const int t = threadIdx.x;
    const int lane = t & 31, w = t >> 5;
    const int g = lane >> 2, q4 = lane & 3;
    const int nw = w * 16;

    // ---- Stage Q [64 d][64 n] into Ps (tf32-rounded) ----
    #pragma unroll
    for (int it = 0; it < 8; it++) {
        int lin = it*128 + t;
        int d = lin >> 4, n4 = (lin & 15) << 2;
        float4 qv = *(const float4*)&Q[base + (size_t)d * 2048 + n0 + n4];
        float* dst = &Ps[d*ST + n4];
        dst[0] = __uint_as_float(f2tf32(qv.x));
        dst[1] = __uint_as_float(f2tf32(qv.y));
        dst[2] = __uint_as_float(f2tf32(qv.z));
        dst[3] = __uint_as_float(f2tf32(qv.w));
    }
    __syncthreads();

    // ---- Extract Q A-fragments (16 n-rows per warp, 8 d-chunks) ----
    uint32_t qa[8][4];
    #pragma unroll
    for (int dc = 0; dc < 8; dc++) {
        qa[dc][0] = __float_as_uint(Ps[(8*dc + q4    )*ST + nw + g    ]);
        qa[dc][1] = __float_as_uint(Ps[(8*dc + q4    )*ST + nw + g + 8]);
        qa[dc][2] = __float_as_uint(Ps[(8*dc + q4 + 4)*ST + nw + g    ]);
        qa[dc][3] = __float_as_uint(Ps[(8*dc + q4 + 4)*ST + nw + g + 8]);
    }

    float o_[8][4];
    #pragma unroll
    for (int dc = 0; dc < 8; dc++)
        #pragma unroll
        for (int j = 0; j < 4; j++) o_[dc][j] = 0.f;
    float l0 = 0.f, l1 = 0.f;

    float* Pw = Ps + w * 16 * ST;  // warp-private P strip [16][ST]

    for (int m0 = 0; m0 < M_; m0 += 64) {
        __syncthreads();  // prior iter's Ks/Vs reads done; iter0: Q extraction done
        // ---- Load K, V tiles [64 d][64 m] (tf32-rounded) ----
        #pragma unroll
        for (int it = 0; it < 8; it++) {
            int lin = it*128 + t;
            int d = lin >> 4, m4 = (lin & 15) << 2;
            const size_t goff = base + (size_t)d * 2048 + m0 + m4;
            float4 kv = *(const float4*)&K[goff];
            float4 vv = *(const float4*)&V[goff];
            float* kd = &Ks[d*ST + m4];
            float* vd = &Vs[d*ST + m4];
            kd[0] = __uint_as_float(f2tf32(kv.x));
            kd[1] = __uint_as_float(f2tf32(kv.y));
            kd[2] = __uint_as_float(f2tf32(kv.z));
            kd[3] = __uint_as_float(f2tf32(kv.w));
            vd[0] = __uint_as_float(f2tf32(vv.x));
            vd[1] = __uint_as_float(f2tf32(vv.y));
            vd[2] = __uint_as_float(f2tf32(vv.z));
            vd[3] = __uint_as_float(f2tf32(vv.w));
        }
        __syncthreads();

        // ---- S = Q^T K : 8 m-chunks of 16x8, accumulate over 8 d-chunks ----
        float s[8][4];
        #pragma unroll
        for (int mc = 0; mc < 8; mc++)
            #pragma unroll
            for (int j = 0; j < 4; j++) s[mc][j] = 0.f;

        #pragma unroll
        for (int dc = 0; dc < 8; dc++) {
            const float* r0 = &Ks[(8*dc + q4    )*ST + g];
            const float* r1 = &Ks[(8*dc + q4 + 4)*ST + g];
            #pragma unroll
            for (int mc = 0; mc < 8; mc++) {
                uint32_t b0 = __float_as_uint(r0[8*mc]);
                uint32_t b1 = __float_as_uint(r1[8*mc]);
                mma_tf32(s[mc], qa[dc], b0, b1, s[mc]);
            }
        }

        // ---- P = exp(S/8); row sums; store P strip (warp-private) ----
        #pragma unroll
        for (int mc = 0; mc < 8; mc++) {
            float e0 = __expf(s[mc][0] * 0.125f);
            float e1 = __expf(s[mc][1] * 0.125f);
            float e2 = __expf(s[mc][2] * 0.125f);
            float e3 = __expf(s[mc][3] * 0.125f);
            l0 += e0 + e1;
            l1 += e2 + e3;
            float2 p01 = make_float2(__uint_as_float(f2tf32(e0)), __uint_as_float(f2tf32(e1)));
            float2 p23 = make_float2(__uint_as_float(f2tf32(e2)), __uint_as_float(f2tf32(e3)));
            *(float2*)&Pw[(g    )*ST + 8*mc + 2*q4] = p01;
            *(float2*)&Pw[(g + 8)*ST + 8*mc + 2*q4] = p23;
        }
        __syncwarp();

        // ---- O += P V : A = P strip, B = V[d][m] fragments ----
        #pragma unroll
        for (int mc = 0; mc < 8; mc++) {
            uint32_t pa[4];
            pa[0] = __float_as_uint(Pw[(g    )*ST + 8*mc + q4    ]);
            pa[1] = __float_as_uint(Pw[(g + 8)*ST + 8*mc + q4    ]);
            pa[2] = __float_as_uint(Pw[(g    )*ST + 8*mc + q4 + 4]);
            pa[3] = __float_as_uint(Pw[(g + 8)*ST + 8*mc + q4 + 4]);
            #pragma unroll
            for (int dc = 0; dc < 8; dc++) {
                const float* vr = &Vs[(8*dc + g)*ST + 8*mc];
                uint32_t b0 = __float_as_uint(vr[q4    ]);
                uint32_t b1 = __float_as_uint(vr[q4 + 4]);
                mma_tf32(o_[dc], pa, b0, b1, o_[dc]);
            }
        }
    }

    // ---- Normalize: reduce row sums over the 4 lanes of each group ----
    l0 += __shfl_xor_sync(0xffffffffu, l0, 1);
    l0 += __shfl_xor_sync(0xffffffffu, l0, 2);
    l1 += __shfl_xor_sync(0xffffffffu, l1, 1);
    l1 += __shfl_xor_sync(0xffffffffu, l1, 2);
    const float inv0 = 1.0f / l0;
    const float inv1 = 1.0f / l1;

    // ---- Stage O as [d][n] into Ks, then coalesced global write ----
    __syncthreads();  // all warps done reading Ks/Vs
    #pragma unroll
    for (int dc = 0; dc < 8; dc++) {
        #pragma unroll
        for (int j = 0; j < 2; j++) {
            int d = 8*dc + 2*q4 + j;
            Ks[d*ST + nw + g    ] = o_[dc][j]     * inv0;
            Ks[d*ST + nw + g + 8] = o_[dc][2 + j] * inv1;
        }
    }
    __syncthreads();
    #pragma unroll
    for (int it = 0; it < 32; it++) {
        int lin = it*128 + t;
        int n = lin & 63, d = lin >> 6;
        O[base + (size_t)d * 2048 + n0 + n] = Ks[d*ST + n];
    }
}

// ---------------------------------------------------------------------------
extern "C" void kernel_launch(void* const* d_in, const int* in_sizes, int n_in,
                              void* d_out, int out_size)
{
    const float* desc1 = (const float*)d_in[0];
    const float* desc2 = (const float*)d_in[1];
    const float* wv    = (const float*)d_in[2];
    const float* Wq    = (const float*)d_in[3];
    const float* bq    = (const float*)d_in[4];
    const float* Wk    = (const float*)d_in[5];
    const float* bk    = (const float*)d_in[6];
    const float* Wv    = (const float*)d_in[7];
    const float* bv    = (const float*)d_in[8];
    const float* Wm    = (const float*)d_in[9];
    const float* bm    = (const float*)d_in[10];
    const float* Wc1   = (const float*)d_in[11];
    const float* bc1   = (const float*)d_in[12];
    const float* gamma = (const float*)d_in[13];
    const float* beta  = (const float*)d_in[14];
    const float* mean  = (const float*)d_in[15];
    const float* var   = (const float*)d_in[16];
    const float* Wc2   = (const float*)d_in[17];
    const float* bc2   = (const float*)d_in[18];
    float* out = (float*)d_out;

    float *q, *k, *v, *attn, *mo, *h;
    cudaGetSymbolAddress((void**)&q,    g_q);
    cudaGetSymbolAddress((void**)&k,    g_k);
    cudaGetSymbolAddress((void**)&v,    g_v);
    cudaGetSymbolAddress((void**)&attn, g_attn);
    cudaGetSymbolAddress((void**)&mo,   g_mo);
    cudaGetSymbolAddress((void**)&h,    g_h);

    const dim3 blk(256);
    const dim3 gp(N_/64, C_/64, B_);
    const dim3 gh(N_/64, 2*C_/64, B_);

    gemm_epi<0><<<gp, blk>>>(Wq, bq, desc1, nullptr, q, C_, C_, C_,
                             nullptr, nullptr, nullptr, nullptr);
    gemm_epi<0><<<gp, blk>>>(Wk, bk, desc2, nullptr, k, C_, C_, C_,
                             nullptr, nullptr, nullptr, nullptr);
    gemm_epi<1><<<gp, blk>>>(Wv, bv, desc2, nullptr, v, C_, C_, C_,
                             wv, nullptr, nullptr, nullptr);

    // Attention: 4 warps/CTA, 64 n-rows, 55296 B dynamic smem
    const int smem_bytes = 3 * TILE_F * sizeof(float);
    cudaFuncSetAttribute(attn_mma, cudaFuncAttributeMaxDynamicSharedMemorySize, smem_bytes);
    attn_mma<<<dim3(N_/64, B_*4), 128, smem_bytes>>>(q, k, v, attn);

    gemm_epi<0><<<gp, blk>>>(Wm, bm, attn, nullptr, mo, C_, C_, C_,
                             nullptr, nullptr, nullptr, nullptr);

    gemm_epi<2><<<gh, blk>>>(Wc1, bc1, desc1, mo, h, 2*C_, 2*C_, C_,
                             gamma, beta, mean, var);

    gemm_epi<3><<<gp, blk>>>(Wc2, bc2, h, nullptr, out, C_, 2*C_, 2*C_,
                             desc1, nullptr, nullptr, nullptr);
}

// round 9
// speedup vs baseline: 1.3903x; 1.3903x over previous
#include <cuda_runtime.h>
#include <math.h>
#include <stdint.h>

static constexpr int B_ = 8;
static constexpr int C_ = 256;
static constexpr int N_ = 2048;
static constexpr int M_ = 2048;

// Scratch (no cudaMalloc allowed)
__device__ float g_q[B_*C_*N_];
__device__ float g_k[B_*C_*M_];
__device__ float g_v[B_*C_*M_];
__device__ float g_attn[B_*C_*N_];
__device__ float g_mo[B_*C_*N_];
__device__ float g_h[B_*2*C_*N_];

// ---------------------------------------------------------------------------
// tf32 helpers
// ---------------------------------------------------------------------------
__device__ __forceinline__ uint32_t f2tf32(float f) {
    uint32_t r;
    asm("cvt.rna.tf32.f32 %0, %1;" : "=r"(r) : "f"(f));
    return r;
}

__device__ __forceinline__ void mma_tf32(
    float d[4], const uint32_t a[4], uint32_t b0, uint32_t b1, const float c[4])
{
    asm volatile(
        "mma.sync.aligned.m16n8k8.row.col.f32.tf32.tf32.f32 "
        "{%0,%1,%2,%3}, {%4,%5,%6,%7}, {%8,%9}, {%10,%11,%12,%13};"
        : "=f"(d[0]), "=f"(d[1]), "=f"(d[2]), "=f"(d[3])
        : "r"(a[0]), "r"(a[1]), "r"(a[2]), "r"(a[3]),
          "r"(b0), "r"(b1),
          "f"(c[0]), "f"(c[1]), "f"(c[2]), "f"(c[3]));
}

// ---------------------------------------------------------------------------
// Tensor-core GEMM with fused epilogue.
// Y[b][o][n] = epi( sum_i W[o][i] * X[b][i][n] + bias[o] )
// Channel i < Ca from Xa, else Xb (concat).
// MODE 0: +bias
// MODE 1: (+bias) * e0[b][n]               (weight_v)
// MODE 2: relu((+bias)*inv[o] + add[o])    (BN)
// MODE 3: (+bias) + e0[b][o][n]            (residual)
// CTA: 128 threads / 4 warps; tile 64 o x 128 n; K-chunk 32.
// Warp w owns o-rows [16w, 16w+16); all 128 n.
// Ws[k][o] stride 70 (A-frag loads conflict-free), Xs[k][n] stride 132.
// ---------------------------------------------------------------------------
static constexpr int WS_ST = 70;
static constexpr int XS_ST = 132;

template<int MODE>
__global__ void __launch_bounds__(128, 4) gemm_mma(
    const float* __restrict__ W, const float* __restrict__ bias,
    const float* __restrict__ Xa, const float* __restrict__ Xb,
    float* __restrict__ Y, int Cout, int Cin, int Ca,
    const float* __restrict__ e0, const float* __restrict__ e1,
    const float* __restrict__ e2, const float* __restrict__ e3)
{
    __shared__ float Ws[32 * WS_ST];
    __shared__ float Xs[32 * XS_ST];

    const int b  = blockIdx.z;
    const int o0 = blockIdx.y * 64;
    const int n0 = blockIdx.x * 128;
    const int t  = threadIdx.x;
    const int lane = t & 31, w = t >> 5;
    const int g = lane >> 2, q4 = lane & 3;
    const int ow = w * 16;
    const int Cb = Cin - Ca;

    // W-load assignment: o = t&63 (lanes of a warp span 32 consecutive rows,
    // so scatter STS banks are o+const -> conflict-free), iq0 = (t>>6)*16.
    const int wlo  = t & 63;
    const int wiq0 = (t >> 6) * 16;

    float acc[16][4];
    #pragma unroll
    for (int nc = 0; nc < 16; nc++)
        #pragma unroll
        for (int j = 0; j < 4; j++) acc[nc][j] = 0.f;

    for (int i0 = 0; i0 < Cin; i0 += 32) {
        __syncthreads();   // prior chunk's fragment reads done
        // ---- Load W tile [64 o][32 k], store transposed Ws[k][o] (tf32) ----
        #pragma unroll
        for (int j = 0; j < 4; j++) {
            const int kk = wiq0 + 4*j;
            float4 w4 = *(const float4*)&W[(size_t)(o0 + wlo) * Cin + i0 + kk];
            Ws[(kk+0)*WS_ST + wlo] = __uint_as_float(f2tf32(w4.x));
            Ws[(kk+1)*WS_ST + wlo] = __uint_as_float(f2tf32(w4.y));
            Ws[(kk+2)*WS_ST + wlo] = __uint_as_float(f2tf32(w4.z));
            Ws[(kk+3)*WS_ST + wlo] = __uint_as_float(f2tf32(w4.w));
        }
        // ---- Load X tile [32 k][128 n] (tf32) ----
        #pragma unroll
        for (int r = 0; r < 8; r++) {
            int lin = r*128 + t;
            int i = lin >> 5, n4 = (lin & 31) << 2;
            int ig = i0 + i;
            float4 xv;
            if (ig < Ca) xv = *(const float4*)&Xa[((size_t)b*Ca + ig) * N_ + n0 + n4];
            else         xv = *(const float4*)&Xb[((size_t)b*Cb + (ig - Ca)) * N_ + n0 + n4];
            float* dst = &Xs[i*XS_ST + n4];
            dst[0] = __uint_as_float(f2tf32(xv.x));
            dst[1] = __uint_as_float(f2tf32(xv.y));
            dst[2] = __uint_as_float(f2tf32(xv.z));
            dst[3] = __uint_as_float(f2tf32(xv.w));
        }
        __syncthreads();

        // ---- 4 sub-chunks of k=8: A from Ws, B from Xs, 16 mmas each ----
        #pragma unroll
        for (int s = 0; s < 4; s++) {
            uint32_t a[4];
            const float* wr0 = &Ws[(8*s + q4    )*WS_ST + ow];
            const float* wr1 = &Ws[(8*s + q4 + 4)*WS_ST + ow];
            a[0] = __float_as_uint(wr0[g]);
            a[1] = __float_as_uint(wr0[g + 8]);
            a[2] = __float_as_uint(wr1[g]);
            a[3] = __float_as_uint(wr1[g + 8]);
            const float* x0 = &Xs[(8*s + q4    )*XS_ST + g];
            const float* x1 = &Xs[(8*s + q4 + 4)*XS_ST + g];
            #pragma unroll
            for (int nc = 0; nc < 16; nc++) {
                uint32_t b0 = __float_as_uint(x0[8*nc]);
                uint32_t b1 = __float_as_uint(x1[8*nc]);
                mma_tf32(acc[nc], a, b0, b1, acc[nc]);
            }
        }
    }

    // ---- Epilogue ----
    const int row0 = o0 + ow + g;
    const int row1 = row0 + 8;
    const float bi0 = bias[row0];
    const float bi1 = bias[row1];
    float inv0, add0, inv1, add1;
    if constexpr (MODE == 2) {
        inv0 = e0[row0] * rsqrtf(e3[row0] + 1e-5f);
        add0 = e1[row0] - e2[row0] * inv0;
        inv1 = e0[row1] * rsqrtf(e3[row1] + 1e-5f);
        add1 = e1[row1] - e2[row1] * inv1;
    }
    const size_t yb0 = ((size_t)b*Cout + row0) * N_;
    const size_t yb1 = ((size_t)b*Cout + row1) * N_;

    #pragma unroll
    for (int nc = 0; nc < 16; nc++) {
        const int n = n0 + 8*nc + 2*q4;
        float2 y0 = make_float2(acc[nc][0] + bi0, acc[nc][1] + bi0);
        float2 y1 = make_float2(acc[nc][2] + bi1, acc[nc][3] + bi1);
        if constexpr (MODE == 1) {
            float2 wv2 = *(const float2*)&e0[(size_t)b * N_ + n];
            y0.x *= wv2.x; y0.y *= wv2.y;
            y1.x *= wv2.x; y1.y *= wv2.y;
        }
        if constexpr (MODE == 2) {
            y0.x = fmaxf(fmaf(y0.x, inv0, add0), 0.f);
            y0.y = fmaxf(fmaf(y0.y, inv0, add0), 0.f);
            y1.x = fmaxf(fmaf(y1.x, inv1, add1), 0.f);
            y1.y = fmaxf(fmaf(y1.y, inv1, add1), 0.f);
        }
        if constexpr (MODE == 3) {
            float2 r0 = *(const float2*)&e0[yb0 + n];
            float2 r1 = *(const float2*)&e0[yb1 + n];
            y0.x += r0.x; y0.y += r0.y;
            y1.x += r1.x; y1.y += r1.y;
        }
        *(float2*)&Y[yb0 + n] = y0;
        *(float2*)&Y[yb1 + n] = y1;
    }
}

// ---------------------------------------------------------------------------
// Attention via mma.sync tf32 (unchanged from R8 — passed at 330us).
// ---------------------------------------------------------------------------
static constexpr int ST = 72;
static constexpr int TILE_F = 64 * ST;

__global__ void __launch_bounds__(128) attn_mma(
    const float* __restrict__ Q, const float* __restrict__ K,
    const float* __restrict__ V, float* __restrict__ O)
{
    extern __shared__ float sm[];
    float* Ks = sm;
    float* Vs = sm + TILE_F;
    float* Ps = sm + 2*TILE_F;

    const int bh = blockIdx.y;
    const int n0 = blockIdx.x * 64;
    const size_t base = (size_t)bh * 64 * 2048;
    const int t = threadIdx.x;
    const int lane = t & 31, w = t >> 5;
    const int g = lane >> 2, q4 = lane & 3;
    const int nw = w * 16;

    #pragma unroll
    for (int it = 0; it < 8; it++) {
        int lin = it*128 + t;
        int d = lin >> 4, n4 = (lin & 15) << 2;
        float4 qv = *(const float4*)&Q[base + (size_t)d * 2048 + n0 + n4];
        float* dst = &Ps[d*ST + n4];
        dst[0] = __uint_as_float(f2tf32(qv.x));
        dst[1] = __uint_as_float(f2tf32(qv.y));
        dst[2] = __uint_as_float(f2tf32(qv.z));
        dst[3] = __uint_as_float(f2tf32(qv.w));
    }
    __syncthreads();

    uint32_t qa[8][4];
    #pragma unroll
    for (int dc = 0; dc < 8; dc++) {
        qa[dc][0] = __float_as_uint(Ps[(8*dc + q4    )*ST + nw + g    ]);
        qa[dc][1] = __float_as_uint(Ps[(8*dc + q4    )*ST + nw + g + 8]);
        qa[dc][2] = __float_as_uint(Ps[(8*dc + q4 + 4)*ST + nw + g    ]);
        qa[dc][3] = __float_as_uint(Ps[(8*dc + q4 + 4)*ST + nw + g + 8]);
    }

    float o_[8][4];
    #pragma unroll
    for (int dc = 0; dc < 8; dc++)
        #pragma unroll
        for (int j = 0; j < 4; j++) o_[dc][j] = 0.f;
    float l0 = 0.f, l1 = 0.f;

    float* Pw = Ps + w * 16 * ST;

    for (int m0 = 0; m0 < M_; m0 += 64) {
        __syncthreads();
        #pragma unroll
        for (int it = 0; it < 8; it++) {
            int lin = it*128 + t;
            int d = lin >> 4, m4 = (lin & 15) << 2;
            const size_t goff = base + (size_t)d * 2048 + m0 + m4;
            float4 kv = *(const float4*)&K[goff];
            float4 vv = *(const float4*)&V[goff];
            float* kd = &Ks[d*ST + m4];
            float* vd = &Vs[d*ST + m4];
            kd[0] = __uint_as_float(f2tf32(kv.x));
            kd[1] = __uint_as_float(f2tf32(kv.y));
            kd[2] = __uint_as_float(f2tf32(kv.z));
            kd[3] = __uint_as_float(f2tf32(kv.w));
            vd[0] = __uint_as_float(f2tf32(vv.x));
            vd[1] = __uint_as_float(f2tf32(vv.y));
            vd[2] = __uint_as_float(f2tf32(vv.z));
            vd[3] = __uint_as_float(f2tf32(vv.w));
        }
        __syncthreads();

        float s[8][4];
        #pragma unroll
        for (int mc = 0; mc < 8; mc++)
            #pragma unroll
            for (int j = 0; j < 4; j++) s[mc][j] = 0.f;

        #pragma unroll
        for (int dc = 0; dc < 8; dc++) {
            const float* r0 = &Ks[(8*dc + q4    )*ST + g];
            const float* r1 = &Ks[(8*dc + q4 + 4)*ST + g];
            #pragma unroll
            for (int mc = 0; mc < 8; mc++) {
                uint32_t b0 = __float_as_uint(r0[8*mc]);
                uint32_t b1 = __float_as_uint(r1[8*mc]);
                mma_tf32(s[mc], qa[dc], b0, b1, s[mc]);
            }
        }

        #pragma unroll
        for (int mc = 0; mc < 8; mc++) {
            float e0 = __expf(s[mc][0] * 0.125f);
            float e1 = __expf(s[mc][1] * 0.125f);
            float e2 = __expf(s[mc][2] * 0.125f);
            float e3 = __expf(s[mc][3] * 0.125f);
            l0 += e0 + e1;
            l1 += e2 + e3;
            float2 p01 = make_float2(__uint_as_float(f2tf32(e0)), __uint_as_float(f2tf32(e1)));
            float2 p23 = make_float2(__uint_as_float(f2tf32(e2)), __uint_as_float(f2tf32(e3)));
            *(float2*)&Pw[(g    )*ST + 8*mc + 2*q4] = p01;
            *(float2*)&Pw[(g + 8)*ST + 8*mc + 2*q4] = p23;
        }
        __syncwarp();

        #pragma unroll
        for (int mc = 0; mc < 8; mc++) {
            uint32_t pa[4];
            pa[0] = __float_as_uint(Pw[(g    )*ST + 8*mc + q4    ]);
            pa[1] = __float_as_uint(Pw[(g + 8)*ST + 8*mc + q4    ]);
            pa[2] = __float_as_uint(Pw[(g    )*ST + 8*mc + q4 + 4]);
            pa[3] = __float_as_uint(Pw[(g + 8)*ST + 8*mc + q4 + 4]);
            #pragma unroll
            for (int dc = 0; dc < 8; dc++) {
                const float* vr = &Vs[(8*dc + g)*ST + 8*mc];
                uint32_t b0 = __float_as_uint(vr[q4    ]);
                uint32_t b1 = __float_as_uint(vr[q4 + 4]);
                mma_tf32(o_[dc], pa, b0, b1, o_[dc]);
            }
        }
    }

    l0 += __shfl_xor_sync(0xffffffffu, l0, 1);
    l0 += __shfl_xor_sync(0xffffffffu, l0, 2);
    l1 += __shfl_xor_sync(0xffffffffu, l1, 1);
    l1 += __shfl_xor_sync(0xffffffffu, l1, 2);
    const float inv0 = 1.0f / l0;
    const float inv1 = 1.0f / l1;

    __syncthreads();
    #pragma unroll
    for (int dc = 0; dc < 8; dc++) {
        #pragma unroll
        for (int j = 0; j < 2; j++) {
            int d = 8*dc + 2*q4 + j;
            Ks[d*ST + nw + g    ] = o_[dc][j]     * inv0;
            Ks[d*ST + nw + g + 8] = o_[dc][2 + j] * inv1;
        }
    }
    __syncthreads();
    #pragma unroll
    for (int it = 0; it < 32; it++) {
        int lin = it*128 + t;
        int n = lin & 63, d = lin >> 6;
        O[base + (size_t)d * 2048 + n0 + n] = Ks[d*ST + n];
    }
}

// ---------------------------------------------------------------------------
extern "C" void kernel_launch(void* const* d_in, const int* in_sizes, int n_in,
                              void* d_out, int out_size)
{
    const float* desc1 = (const float*)d_in[0];
    const float* desc2 = (const float*)d_in[1];
    const float* wv    = (const float*)d_in[2];
    const float* Wq    = (const float*)d_in[3];
    const float* bq    = (const float*)d_in[4];
    const float* Wk    = (const float*)d_in[5];
    const float* bk    = (const float*)d_in[6];
    const float* Wv    = (const float*)d_in[7];
    const float* bv    = (const float*)d_in[8];
    const float* Wm    = (const float*)d_in[9];
    const float* bm    = (const float*)d_in[10];
    const float* Wc1   = (const float*)d_in[11];
    const float* bc1   = (const float*)d_in[12];
    const float* gamma = (const float*)d_in[13];
    const float* beta  = (const float*)d_in[14];
    const float* mean  = (const float*)d_in[15];
    const float* var   = (const float*)d_in[16];
    const float* Wc2   = (const float*)d_in[17];
    const float* bc2   = (const float*)d_in[18];
    float* out = (float*)d_out;

    float *q, *k, *v, *attn, *mo, *h;
    cudaGetSymbolAddress((void**)&q,    g_q);
    cudaGetSymbolAddress((void**)&k,    g_k);
    cudaGetSymbolAddress((void**)&v,    g_v);
    cudaGetSymbolAddress((void**)&attn, g_attn);
    cudaGetSymbolAddress((void**)&mo,   g_mo);
    cudaGetSymbolAddress((void**)&h,    g_h);

    const dim3 blk(128);
    const dim3 gp(N_/128, C_/64, B_);    // 16 x 4 x 8
    const dim3 gh(N_/128, 2*C_/64, B_);  // 16 x 8 x 8

    gemm_mma<0><<<gp, blk>>>(Wq, bq, desc1, nullptr, q, C_, C_, C_,
                             nullptr, nullptr, nullptr, nullptr);
    gemm_mma<0><<<gp, blk>>>(Wk, bk, desc2, nullptr, k, C_, C_, C_,
                             nullptr, nullptr, nullptr, nullptr);
    gemm_mma<1><<<gp, blk>>>(Wv, bv, desc2, nullptr, v, C_, C_, C_,
                             wv, nullptr, nullptr, nullptr);

    const int smem_bytes = 3 * TILE_F * sizeof(float);
    cudaFuncSetAttribute(attn_mma, cudaFuncAttributeMaxDynamicSharedMemorySize, smem_bytes);
    attn_mma<<<dim3(N_/64, B_*4), 128, smem_bytes>>>(q, k, v, attn);

    gemm_mma<0><<<gp, blk>>>(Wm, bm, attn, nullptr, mo, C_, C_, C_,
                             nullptr, nullptr, nullptr, nullptr);

    gemm_mma<2><<<gh, blk>>>(Wc1, bc1, desc1, mo, h, 2*C_, 2*C_, C_,
                             gamma, beta, mean, var);

    gemm_mma<3><<<gp, blk>>>(Wc2, bc2, h, nullptr, out, C_, 2*C_, 2*C_,
                             desc1, nullptr, nullptr, nullptr);
}